// round 6
// baseline (speedup 1.0000x reference)
#include <cuda_runtime.h>
#include <cstdint>

#define N_NODES 50000
#define N_EDGES 800000
#define NFEAT   128
#define DEG_CAP 96
#define BLK_M   64      // nodes per block
#define AS_STRIDE 132   // A-frag LDS conflict-free
#define WS_STRIDE 136   // B-frag LDS conflict-free

// Device-global scratch (allocation forbidden). Zero-initialized at load.
// g_cnt invariant: zero on entry to every kernel_launch call (fused kernel
// re-zeroes its own nodes after consuming).
__device__ int g_cnt[N_NODES];
__device__ int g_bin[(size_t)N_NODES * DEG_CAP];
__device__ unsigned g_whi[NFEAT * NFEAT];
__device__ unsigned g_wlo[NFEAT * NFEAT];

// ---------------------------------------------------------------------------
// tf32 helpers
// ---------------------------------------------------------------------------
__device__ __forceinline__ void tf32_split(float x, unsigned& hi, unsigned& lo) {
    asm("cvt.rna.tf32.f32 %0, %1;" : "=r"(hi) : "f"(x));
    float r = x - __uint_as_float(hi);
    asm("cvt.rna.tf32.f32 %0, %1;" : "=r"(lo) : "f"(r));
}

__device__ __forceinline__ void mma_tf32(float* c, const unsigned* a, const unsigned* b) {
    asm("mma.sync.aligned.m16n8k8.row.col.f32.tf32.tf32.f32 "
        "{%0,%1,%2,%3}, {%4,%5,%6,%7}, {%8,%9}, {%0,%1,%2,%3};"
        : "+f"(c[0]), "+f"(c[1]), "+f"(c[2]), "+f"(c[3])
        : "r"(a[0]), "r"(a[1]), "r"(a[2]), "r"(a[3]), "r"(b[0]), "r"(b[1]));
}

// ---------------------------------------------------------------------------
// Kernel 1: prep = W tf32 split (first 16384 ids) + binned edge fill.
// ---------------------------------------------------------------------------
__global__ void prep_kernel(const float* __restrict__ Wm,
                            const int*   __restrict__ src,
                            const int*   __restrict__ dst) {
    int gid = blockIdx.x * blockDim.x + threadIdx.x;

    if (gid < NFEAT * NFEAT) {
        float x = Wm[gid];
        unsigned hi, lo;
        tf32_split(x, hi, lo);
        g_whi[gid] = hi;
        g_wlo[gid] = lo;
    }

    if (gid < N_EDGES / 4) {
        int4 d4 = reinterpret_cast<const int4*>(dst)[gid];
        int4 s4 = reinterpret_cast<const int4*>(src)[gid];
        int p;
        p = atomicAdd(&g_cnt[d4.x], 1); if (p < DEG_CAP) g_bin[(size_t)d4.x * DEG_CAP + p] = s4.x;
        p = atomicAdd(&g_cnt[d4.y], 1); if (p < DEG_CAP) g_bin[(size_t)d4.y * DEG_CAP + p] = s4.y;
        p = atomicAdd(&g_cnt[d4.z], 1); if (p < DEG_CAP) g_bin[(size_t)d4.z * DEG_CAP + p] = s4.z;
        p = atomicAdd(&g_cnt[d4.w], 1); if (p < DEG_CAP) g_bin[(size_t)d4.w * DEG_CAP + p] = s4.w;
    }
}

// ---------------------------------------------------------------------------
// Kernel 2: fused gather + 3xTF32 MMA GEMM + bias + relu.
// Block = 64 nodes, 256 threads (8 warps), 3 CTAs/SM (68.6 KB smem, <=85 regs).
// Phase 1: warp w gathers nodes [w*8, w*8+8): one coalesced index LDG per
//          32 edges + shfl broadcast; feature rows unroll-8 float4/lane.
// Phase 2: warp grid 2(m) x 4(n), warp tile 32x32, m16n8k8 tf32 MMA,
//          3-pass hi/lo split (fp32-class accuracy).
// ---------------------------------------------------------------------------
__global__ __launch_bounds__(256, 3)
void fused_gather_gemm_kernel(const float* __restrict__ feature,
                              const float* __restrict__ bias,
                              float* __restrict__ out) {
    extern __shared__ float sm[];
    float*    As   = sm;                                                  // [64][AS_STRIDE]
    unsigned* sWhi = reinterpret_cast<unsigned*>(sm + BLK_M * AS_STRIDE); // [32][WS_STRIDE]
    unsigned* sWlo = sWhi + 32 * WS_STRIDE;                               // [32][WS_STRIDE]

    const int tid  = threadIdx.x;
    const int lane = tid & 31;
    const int warp = tid >> 5;
    const int block_m = blockIdx.x * BLK_M;
    const unsigned FULL = 0xffffffffu;

    // ---- Pre-issue W tile kb=0 into smem (latency hides under gather) ----
    {
        #pragma unroll
        for (int r = 0; r < 4; r++) {
            int idx = tid + r * 256;
            int n   = idx >> 3;
            int kq  = idx & 7;
            uint4 vh = *reinterpret_cast<const uint4*>(g_whi + n * NFEAT + kq * 4);
            sWhi[(kq * 4 + 0) * WS_STRIDE + n] = vh.x;
            sWhi[(kq * 4 + 1) * WS_STRIDE + n] = vh.y;
            sWhi[(kq * 4 + 2) * WS_STRIDE + n] = vh.z;
            sWhi[(kq * 4 + 3) * WS_STRIDE + n] = vh.w;
            uint4 vl = *reinterpret_cast<const uint4*>(g_wlo + n * NFEAT + kq * 4);
            sWlo[(kq * 4 + 0) * WS_STRIDE + n] = vl.x;
            sWlo[(kq * 4 + 1) * WS_STRIDE + n] = vl.y;
            sWlo[(kq * 4 + 2) * WS_STRIDE + n] = vl.z;
            sWlo[(kq * 4 + 3) * WS_STRIDE + n] = vl.w;
        }
    }

    // ---- Phase 1: gather BLK_M aggregated rows into As ----
    const float* fb = feature + lane * 4;
    const int node0 = block_m + warp * 8;

    // counts for my 8 nodes (lane t holds count of node0+t)
    int cnt_all = 0;
    if (lane < 8) {
        int nd = node0 + lane;
        if (nd < N_NODES) {
            int c = g_cnt[nd];
            cnt_all = (c > DEG_CAP) ? DEG_CAP : c;
        }
    }

    // prefetch first index batch
    int sidx_next = 0;
    if (node0 < N_NODES)
        sidx_next = g_bin[(size_t)node0 * DEG_CAP + lane];

    #pragma unroll 1
    for (int t = 0; t < 8; t++) {
        const int node = node0 + t;
        const int cnt  = __shfl_sync(FULL, cnt_all, t);
        const int sidx = sidx_next;
        // prefetch next node's batch
        if (t + 1 < 8 && node0 + t + 1 < N_NODES)
            sidx_next = g_bin[(size_t)(node0 + t + 1) * DEG_CAP + lane];

        float4 aA = make_float4(0.f, 0.f, 0.f, 0.f);
        float4 aB = make_float4(0.f, 0.f, 0.f, 0.f);

        const int nb = (cnt < 32) ? cnt : 32;
        int e = 0;
        for (; e + 8 <= nb; e += 8) {
            int s0 = __shfl_sync(FULL, sidx, e + 0);
            int s1 = __shfl_sync(FULL, sidx, e + 1);
            int s2 = __shfl_sync(FULL, sidx, e + 2);
            int s3 = __shfl_sync(FULL, sidx, e + 3);
            int s4 = __shfl_sync(FULL, sidx, e + 4);
            int s5 = __shfl_sync(FULL, sidx, e + 5);
            int s6 = __shfl_sync(FULL, sidx, e + 6);
            int s7 = __shfl_sync(FULL, sidx, e + 7);
            float4 v0 = *reinterpret_cast<const float4*>(fb + (size_t)s0 * NFEAT);
            float4 v1 = *reinterpret_cast<const float4*>(fb + (size_t)s1 * NFEAT);
            float4 v2 = *reinterpret_cast<const float4*>(fb + (size_t)s2 * NFEAT);
            float4 v3 = *reinterpret_cast<const float4*>(fb + (size_t)s3 * NFEAT);
            float4 v4 = *reinterpret_cast<const float4*>(fb + (size_t)s4 * NFEAT);
            float4 v5 = *reinterpret_cast<const float4*>(fb + (size_t)s5 * NFEAT);
            float4 v6 = *reinterpret_cast<const float4*>(fb + (size_t)s6 * NFEAT);
            float4 v7 = *reinterpret_cast<const float4*>(fb + (size_t)s7 * NFEAT);
            aA.x += (v0.x + v2.x) + (v4.x + v6.x);
            aA.y += (v0.y + v2.y) + (v4.y + v6.y);
            aA.z += (v0.z + v2.z) + (v4.z + v6.z);
            aA.w += (v0.w + v2.w) + (v4.w + v6.w);
            aB.x += (v1.x + v3.x) + (v5.x + v7.x);
            aB.y += (v1.y + v3.y) + (v5.y + v7.y);
            aB.z += (v1.z + v3.z) + (v5.z + v7.z);
            aB.w += (v1.w + v3.w) + (v5.w + v7.w);
        }
        for (; e < nb; e++) {
            int s = __shfl_sync(FULL, sidx, e);
            float4 v = *reinterpret_cast<const float4*>(fb + (size_t)s * NFEAT);
            aA.x += v.x; aA.y += v.y; aA.z += v.z; aA.w += v.w;
        }
        // rare: degree > 32 (further 32-wide batches; base+lane <= 95 < DEG_CAP)
        for (int base = 32; base < cnt; base += 32) {
            int sx = g_bin[(size_t)node * DEG_CAP + base + lane];
            int nb2 = cnt - base; if (nb2 > 32) nb2 = 32;
            for (int e2 = 0; e2 < nb2; e2++) {
                int s = __shfl_sync(FULL, sx, e2);
                float4 v = *reinterpret_cast<const float4*>(fb + (size_t)s * NFEAT);
                aB.x += v.x; aB.y += v.y; aB.z += v.z; aB.w += v.w;
            }
        }

        float4 acc4;
        acc4.x = aA.x + aB.x; acc4.y = aA.y + aB.y;
        acc4.z = aA.z + aB.z; acc4.w = aA.w + aB.w;
        *reinterpret_cast<float4*>(&As[(warp * 8 + t) * AS_STRIDE + lane * 4]) = acc4;
    }
    __syncthreads();

    // Re-zero counters for next replay (this block owns these nodes; their
    // counts were read before the barrier above).
    if (tid < BLK_M) {
        int node = block_m + tid;
        if (node < N_NODES) g_cnt[node] = 0;
    }

    // ---- Phase 2: GEMM out = relu(As @ W^T + b), 3xTF32 ----
    const int wm = (warp >> 2) * 32;   // 0, 32
    const int wn = (warp & 3) * 32;    // 0, 32, 64, 96
    const int g  = lane >> 2;
    const int t4 = lane & 3;

    float acc[2][4][4];
    #pragma unroll
    for (int mt = 0; mt < 2; mt++)
        #pragma unroll
        for (int nt = 0; nt < 4; nt++)
            #pragma unroll
            for (int q = 0; q < 4; q++)
                acc[mt][nt][q] = 0.f;

    #pragma unroll 1
    for (int kb = 0; kb < 4; kb++) {
        __syncthreads();   // W tile kb ready (preloaded last iter / pre-gather)

        #pragma unroll
        for (int kk = 0; kk < 4; kk++) {
            const int k0 = kk * 8;
            const int kg = kb * 32 + k0;

            unsigned ahi[2][4], alo[2][4];
            #pragma unroll
            for (int mt = 0; mt < 2; mt++) {
                const float* ap = &As[(wm + mt * 16 + g) * AS_STRIDE + kg + t4];
                tf32_split(ap[0],                  ahi[mt][0], alo[mt][0]);
                tf32_split(ap[8 * AS_STRIDE],      ahi[mt][1], alo[mt][1]);
                tf32_split(ap[4],                  ahi[mt][2], alo[mt][2]);
                tf32_split(ap[8 * AS_STRIDE + 4],  ahi[mt][3], alo[mt][3]);
            }

            #pragma unroll
            for (int nt = 0; nt < 4; nt++) {
                const int bb = (k0 + t4) * WS_STRIDE + wn + nt * 8 + g;
                unsigned bh[2], bl[2];
                bh[0] = sWhi[bb];
                bh[1] = sWhi[bb + 4 * WS_STRIDE];
                bl[0] = sWlo[bb];
                bl[1] = sWlo[bb + 4 * WS_STRIDE];
                #pragma unroll
                for (int mt = 0; mt < 2; mt++) {
                    mma_tf32(acc[mt][nt], ahi[mt], bl);
                    mma_tf32(acc[mt][nt], alo[mt], bh);
                    mma_tf32(acc[mt][nt], ahi[mt], bh);
                }
            }
        }
        __syncthreads();   // done reading tile kb

        // load W tile kb+1
        if (kb < 3) {
            #pragma unroll
            for (int r = 0; r < 4; r++) {
                int idx = tid + r * 256;
                int n   = idx >> 3;
                int kq  = idx & 7;
                const unsigned* ph = g_whi + n * NFEAT + (kb + 1) * 32 + kq * 4;
                uint4 vh = *reinterpret_cast<const uint4*>(ph);
                sWhi[(kq * 4 + 0) * WS_STRIDE + n] = vh.x;
                sWhi[(kq * 4 + 1) * WS_STRIDE + n] = vh.y;
                sWhi[(kq * 4 + 2) * WS_STRIDE + n] = vh.z;
                sWhi[(kq * 4 + 3) * WS_STRIDE + n] = vh.w;
                const unsigned* pl = g_wlo + n * NFEAT + (kb + 1) * 32 + kq * 4;
                uint4 vl = *reinterpret_cast<const uint4*>(pl);
                sWlo[(kq * 4 + 0) * WS_STRIDE + n] = vl.x;
                sWlo[(kq * 4 + 1) * WS_STRIDE + n] = vl.y;
                sWlo[(kq * 4 + 2) * WS_STRIDE + n] = vl.z;
                sWlo[(kq * 4 + 3) * WS_STRIDE + n] = vl.w;
            }
        }
    }

    // ---- Epilogue: bias + relu, float2 stores ----
    #pragma unroll
    for (int mt = 0; mt < 2; mt++) {
        int r0 = block_m + wm + mt * 16 + g;
        int r1 = r0 + 8;
        #pragma unroll
        for (int nt = 0; nt < 4; nt++) {
            int c0 = wn + nt * 8 + 2 * t4;
            float2 bv = *reinterpret_cast<const float2*>(bias + c0);
            if (r0 < N_NODES) {
                float2 o;
                o.x = fmaxf(acc[mt][nt][0] + bv.x, 0.f);
                o.y = fmaxf(acc[mt][nt][1] + bv.y, 0.f);
                *reinterpret_cast<float2*>(out + (size_t)r0 * NFEAT + c0) = o;
            }
            if (r1 < N_NODES) {
                float2 o;
                o.x = fmaxf(acc[mt][nt][2] + bv.x, 0.f);
                o.y = fmaxf(acc[mt][nt][3] + bv.y, 0.f);
                *reinterpret_cast<float2*>(out + (size_t)r1 * NFEAT + c0) = o;
            }
        }
    }
}

// ---------------------------------------------------------------------------
// kernel_launch
// Inputs: feature [N,128] f32, src_idx [E] i32, dst_idx [E] i32,
//         W [128,128] f32, b [128] f32.  Output: [N,128] f32.
// ---------------------------------------------------------------------------
extern "C" void kernel_launch(void* const* d_in, const int* in_sizes, int n_in,
                              void* d_out, int out_size) {
    const float* feature = (const float*)d_in[0];
    const int*   src_idx = (const int*)d_in[1];
    const int*   dst_idx = (const int*)d_in[2];
    const float* Wm      = (const float*)d_in[3];
    const float* bias    = (const float*)d_in[4];
    float*       out     = (float*)d_out;

    const int SMEM_FUSED = (BLK_M * AS_STRIDE + 2 * 32 * WS_STRIDE) * 4;  // 68608 B
    cudaFuncSetAttribute(fused_gather_gemm_kernel,
                         cudaFuncAttributeMaxDynamicSharedMemorySize, SMEM_FUSED);

    // 1) prep: W split + binned fill (g_cnt zero on entry)
    int prep_threads = N_EDGES / 4;                    // 200000 (> 16384)
    prep_kernel<<<(prep_threads + 255) / 256, 256>>>(Wm, src_idx, dst_idx);

    // 2) fused gather + GEMM + bias + relu
    int fused_blocks = (N_NODES + BLK_M - 1) / BLK_M;
    fused_gather_gemm_kernel<<<fused_blocks, 256, SMEM_FUSED>>>(
        feature, bias, out);
}

// round 7
// speedup vs baseline: 1.0633x; 1.0633x over previous
#include <cuda_runtime.h>
#include <cstdint>

#define N_NODES 50000
#define N_EDGES 800000
#define NFEAT   128
#define DEG_CAP 96
#define AS_STRIDE 132   // A-frag LDS conflict-free
#define WS_STRIDE 136   // B-frag LDS conflict-free

// Device-global scratch (allocation forbidden). Zero-initialized at load.
// g_cnt invariant: zero on entry to every kernel_launch call (gather kernel
// re-zeroes each node's counter after consuming it).
__device__ int g_cnt[N_NODES];
__device__ int g_bin[(size_t)N_NODES * DEG_CAP];
__device__ unsigned g_whi[NFEAT * NFEAT];
__device__ unsigned g_wlo[NFEAT * NFEAT];
__device__ float g_agg[(size_t)N_NODES * NFEAT];

// ---------------------------------------------------------------------------
// tf32 helpers
// ---------------------------------------------------------------------------
__device__ __forceinline__ void tf32_split(float x, unsigned& hi, unsigned& lo) {
    asm("cvt.rna.tf32.f32 %0, %1;" : "=r"(hi) : "f"(x));
    float r = x - __uint_as_float(hi);
    asm("cvt.rna.tf32.f32 %0, %1;" : "=r"(lo) : "f"(r));
}

__device__ __forceinline__ void mma_tf32(float* c, const unsigned* a, const unsigned* b) {
    asm("mma.sync.aligned.m16n8k8.row.col.f32.tf32.tf32.f32 "
        "{%0,%1,%2,%3}, {%4,%5,%6,%7}, {%8,%9}, {%0,%1,%2,%3};"
        : "+f"(c[0]), "+f"(c[1]), "+f"(c[2]), "+f"(c[3])
        : "r"(a[0]), "r"(a[1]), "r"(a[2]), "r"(a[3]), "r"(b[0]), "r"(b[1]));
}

// ---------------------------------------------------------------------------
// Kernel 1: prep = W tf32 split (first 16384 ids) + binned edge fill.
// ---------------------------------------------------------------------------
__global__ void prep_kernel(const float* __restrict__ Wm,
                            const int*   __restrict__ src,
                            const int*   __restrict__ dst) {
    int gid = blockIdx.x * blockDim.x + threadIdx.x;

    if (gid < NFEAT * NFEAT) {
        float x = Wm[gid];
        unsigned hi, lo;
        tf32_split(x, hi, lo);
        g_whi[gid] = hi;
        g_wlo[gid] = lo;
    }

    if (gid < N_EDGES / 4) {
        int4 d4 = reinterpret_cast<const int4*>(dst)[gid];
        int4 s4 = reinterpret_cast<const int4*>(src)[gid];
        int p;
        p = atomicAdd(&g_cnt[d4.x], 1); if (p < DEG_CAP) g_bin[(size_t)d4.x * DEG_CAP + p] = s4.x;
        p = atomicAdd(&g_cnt[d4.y], 1); if (p < DEG_CAP) g_bin[(size_t)d4.y * DEG_CAP + p] = s4.y;
        p = atomicAdd(&g_cnt[d4.z], 1); if (p < DEG_CAP) g_bin[(size_t)d4.z * DEG_CAP + p] = s4.z;
        p = atomicAdd(&g_cnt[d4.w], 1); if (p < DEG_CAP) g_bin[(size_t)d4.w * DEG_CAP + p] = s4.w;
    }
}

// ---------------------------------------------------------------------------
// Kernel 2: gather — one warp per node, no smem, no barriers.
// Warp loads up to 32 bin indices in ONE coalesced LDG, broadcasts via shfl,
// accumulates feature rows float4/lane with unroll-8 (two chains), writes the
// aggregated row to g_agg, then re-zeroes the node's counter.
// ---------------------------------------------------------------------------
__global__ __launch_bounds__(256, 4)
void gather_kernel(const float* __restrict__ feature) {
    const int node = (int)((blockIdx.x * (size_t)blockDim.x + threadIdx.x) >> 5);
    const int lane = threadIdx.x & 31;
    const unsigned FULL = 0xffffffffu;
    if (node >= N_NODES) return;

    int cnt = g_cnt[node];
    if (cnt > DEG_CAP) cnt = DEG_CAP;
    const int sidx = g_bin[(size_t)node * DEG_CAP + lane];
    const float* fb = feature + lane * 4;

    float4 aA = make_float4(0.f, 0.f, 0.f, 0.f);
    float4 aB = make_float4(0.f, 0.f, 0.f, 0.f);

    const int nb = (cnt < 32) ? cnt : 32;
    int e = 0;
    for (; e + 8 <= nb; e += 8) {
        int s0 = __shfl_sync(FULL, sidx, e + 0);
        int s1 = __shfl_sync(FULL, sidx, e + 1);
        int s2 = __shfl_sync(FULL, sidx, e + 2);
        int s3 = __shfl_sync(FULL, sidx, e + 3);
        int s4 = __shfl_sync(FULL, sidx, e + 4);
        int s5 = __shfl_sync(FULL, sidx, e + 5);
        int s6 = __shfl_sync(FULL, sidx, e + 6);
        int s7 = __shfl_sync(FULL, sidx, e + 7);
        float4 v0 = *reinterpret_cast<const float4*>(fb + (size_t)s0 * NFEAT);
        float4 v1 = *reinterpret_cast<const float4*>(fb + (size_t)s1 * NFEAT);
        float4 v2 = *reinterpret_cast<const float4*>(fb + (size_t)s2 * NFEAT);
        float4 v3 = *reinterpret_cast<const float4*>(fb + (size_t)s3 * NFEAT);
        float4 v4 = *reinterpret_cast<const float4*>(fb + (size_t)s4 * NFEAT);
        float4 v5 = *reinterpret_cast<const float4*>(fb + (size_t)s5 * NFEAT);
        float4 v6 = *reinterpret_cast<const float4*>(fb + (size_t)s6 * NFEAT);
        float4 v7 = *reinterpret_cast<const float4*>(fb + (size_t)s7 * NFEAT);
        aA.x += (v0.x + v2.x) + (v4.x + v6.x);
        aA.y += (v0.y + v2.y) + (v4.y + v6.y);
        aA.z += (v0.z + v2.z) + (v4.z + v6.z);
        aA.w += (v0.w + v2.w) + (v4.w + v6.w);
        aB.x += (v1.x + v3.x) + (v5.x + v7.x);
        aB.y += (v1.y + v3.y) + (v5.y + v7.y);
        aB.z += (v1.z + v3.z) + (v5.z + v7.z);
        aB.w += (v1.w + v3.w) + (v5.w + v7.w);
    }
    for (; e < nb; e++) {
        int s = __shfl_sync(FULL, sidx, e);
        float4 v = *reinterpret_cast<const float4*>(fb + (size_t)s * NFEAT);
        aA.x += v.x; aA.y += v.y; aA.z += v.z; aA.w += v.w;
    }
    // rare: degree > 32 (base+lane <= 95 < DEG_CAP so the load is in-bounds)
    for (int base = 32; base < cnt; base += 32) {
        int sx = g_bin[(size_t)node * DEG_CAP + base + lane];
        int nb2 = cnt - base; if (nb2 > 32) nb2 = 32;
        for (int e2 = 0; e2 < nb2; e2++) {
            int s = __shfl_sync(FULL, sx, e2);
            float4 v = *reinterpret_cast<const float4*>(fb + (size_t)s * NFEAT);
            aB.x += v.x; aB.y += v.y; aB.z += v.z; aB.w += v.w;
        }
    }

    float4 r;
    r.x = aA.x + aB.x; r.y = aA.y + aB.y;
    r.z = aA.z + aB.z; r.w = aA.w + aB.w;
    *reinterpret_cast<float4*>(g_agg + (size_t)node * NFEAT + lane * 4) = r;

    if (lane == 0) g_cnt[node] = 0;   // restore invariant for next replay
}

// ---------------------------------------------------------------------------
// Kernel 3: GEMM out = relu(g_agg @ W^T + b), 3xTF32 MMA.
// Block = 128 rows, 256 threads, occ 2. Warp grid 4(m) x 2(n).
// ---------------------------------------------------------------------------
__global__ __launch_bounds__(256, 2)
void gemm_kernel(const float* __restrict__ bias,
                 float* __restrict__ out) {
    extern __shared__ float sm[];
    float*    As   = sm;                                                // [128][AS_STRIDE]
    unsigned* sWhi = reinterpret_cast<unsigned*>(sm + 128 * AS_STRIDE); // [32][WS_STRIDE]
    unsigned* sWlo = sWhi + 32 * WS_STRIDE;                             // [32][WS_STRIDE]

    const int tid  = threadIdx.x;
    const int lane = tid & 31;
    const int warp = tid >> 5;
    const int block_m = blockIdx.x * 128;

    // Stage As (128 x 128) from g_agg — 16 float4 per thread, coalesced.
    #pragma unroll
    for (int r = 0; r < 16; r++) {
        int idx = tid + r * 256;          // 0..4095
        int row = idx >> 5;               // 0..127
        int q   = idx & 31;               // float4 within row
        int grow = block_m + row;
        float4 v = make_float4(0.f, 0.f, 0.f, 0.f);
        if (grow < N_NODES)
            v = *reinterpret_cast<const float4*>(g_agg + (size_t)grow * NFEAT + q * 4);
        *reinterpret_cast<float4*>(&As[row * AS_STRIDE + q * 4]) = v;
    }

    // Stage W tile kb=0.
    #pragma unroll
    for (int r = 0; r < 4; r++) {
        int idx = tid + r * 256;
        int n   = idx >> 3;
        int kq  = idx & 7;
        uint4 vh = *reinterpret_cast<const uint4*>(g_whi + n * NFEAT + kq * 4);
        sWhi[(kq * 4 + 0) * WS_STRIDE + n] = vh.x;
        sWhi[(kq * 4 + 1) * WS_STRIDE + n] = vh.y;
        sWhi[(kq * 4 + 2) * WS_STRIDE + n] = vh.z;
        sWhi[(kq * 4 + 3) * WS_STRIDE + n] = vh.w;
        uint4 vl = *reinterpret_cast<const uint4*>(g_wlo + n * NFEAT + kq * 4);
        sWlo[(kq * 4 + 0) * WS_STRIDE + n] = vl.x;
        sWlo[(kq * 4 + 1) * WS_STRIDE + n] = vl.y;
        sWlo[(kq * 4 + 2) * WS_STRIDE + n] = vl.z;
        sWlo[(kq * 4 + 3) * WS_STRIDE + n] = vl.w;
    }

    const int wm = (warp >> 1) * 32;
    const int wn = (warp & 1) * 64;
    const int g  = lane >> 2;
    const int t4 = lane & 3;

    float acc[2][8][4];
    #pragma unroll
    for (int mt = 0; mt < 2; mt++)
        #pragma unroll
        for (int nt = 0; nt < 8; nt++)
            #pragma unroll
            for (int q = 0; q < 4; q++)
                acc[mt][nt][q] = 0.f;

    #pragma unroll 1
    for (int kb = 0; kb < 4; kb++) {
        __syncthreads();   // As + W tile kb ready

        #pragma unroll
        for (int kk = 0; kk < 4; kk++) {
            const int k0 = kk * 8;
            const int kg = kb * 32 + k0;

            unsigned ahi[2][4], alo[2][4];
            #pragma unroll
            for (int mt = 0; mt < 2; mt++) {
                const float* ap = &As[(wm + mt * 16 + g) * AS_STRIDE + kg + t4];
                tf32_split(ap[0],                  ahi[mt][0], alo[mt][0]);
                tf32_split(ap[8 * AS_STRIDE],      ahi[mt][1], alo[mt][1]);
                tf32_split(ap[4],                  ahi[mt][2], alo[mt][2]);
                tf32_split(ap[8 * AS_STRIDE + 4],  ahi[mt][3], alo[mt][3]);
            }

            #pragma unroll
            for (int nt = 0; nt < 8; nt++) {
                const int bb = (k0 + t4) * WS_STRIDE + wn + nt * 8 + g;
                unsigned bh[2], bl[2];
                bh[0] = sWhi[bb];
                bh[1] = sWhi[bb + 4 * WS_STRIDE];
                bl[0] = sWlo[bb];
                bl[1] = sWlo[bb + 4 * WS_STRIDE];
                #pragma unroll
                for (int mt = 0; mt < 2; mt++) {
                    mma_tf32(acc[mt][nt], ahi[mt], bl);
                    mma_tf32(acc[mt][nt], alo[mt], bh);
                    mma_tf32(acc[mt][nt], ahi[mt], bh);
                }
            }
        }
        __syncthreads();   // done reading tile kb

        if (kb < 3) {
            #pragma unroll
            for (int r = 0; r < 4; r++) {
                int idx = tid + r * 256;
                int n   = idx >> 3;
                int kq  = idx & 7;
                const unsigned* ph = g_whi + n * NFEAT + (kb + 1) * 32 + kq * 4;
                uint4 vh = *reinterpret_cast<const uint4*>(ph);
                sWhi[(kq * 4 + 0) * WS_STRIDE + n] = vh.x;
                sWhi[(kq * 4 + 1) * WS_STRIDE + n] = vh.y;
                sWhi[(kq * 4 + 2) * WS_STRIDE + n] = vh.z;
                sWhi[(kq * 4 + 3) * WS_STRIDE + n] = vh.w;
                const unsigned* pl = g_wlo + n * NFEAT + (kb + 1) * 32 + kq * 4;
                uint4 vl = *reinterpret_cast<const uint4*>(pl);
                sWlo[(kq * 4 + 0) * WS_STRIDE + n] = vl.x;
                sWlo[(kq * 4 + 1) * WS_STRIDE + n] = vl.y;
                sWlo[(kq * 4 + 2) * WS_STRIDE + n] = vl.z;
                sWlo[(kq * 4 + 3) * WS_STRIDE + n] = vl.w;
            }
        }
    }

    // ---- Epilogue: bias + relu, float2 stores ----
    #pragma unroll
    for (int mt = 0; mt < 2; mt++) {
        int r0 = block_m + wm + mt * 16 + g;
        int r1 = r0 + 8;
        #pragma unroll
        for (int nt = 0; nt < 8; nt++) {
            int c0 = wn + nt * 8 + 2 * t4;
            float2 bv = *reinterpret_cast<const float2*>(bias + c0);
            if (r0 < N_NODES) {
                float2 o;
                o.x = fmaxf(acc[mt][nt][0] + bv.x, 0.f);
                o.y = fmaxf(acc[mt][nt][1] + bv.y, 0.f);
                *reinterpret_cast<float2*>(out + (size_t)r0 * NFEAT + c0) = o;
            }
            if (r1 < N_NODES) {
                float2 o;
                o.x = fmaxf(acc[mt][nt][2] + bv.x, 0.f);
                o.y = fmaxf(acc[mt][nt][3] + bv.y, 0.f);
                *reinterpret_cast<float2*>(out + (size_t)r1 * NFEAT + c0) = o;
            }
        }
    }
}

// ---------------------------------------------------------------------------
// kernel_launch
// Inputs: feature [N,128] f32, src_idx [E] i32, dst_idx [E] i32,
//         W [128,128] f32, b [128] f32.  Output: [N,128] f32.
// ---------------------------------------------------------------------------
extern "C" void kernel_launch(void* const* d_in, const int* in_sizes, int n_in,
                              void* d_out, int out_size) {
    const float* feature = (const float*)d_in[0];
    const int*   src_idx = (const int*)d_in[1];
    const int*   dst_idx = (const int*)d_in[2];
    const float* Wm      = (const float*)d_in[3];
    const float* bias    = (const float*)d_in[4];
    float*       out     = (float*)d_out;

    const int SMEM_GEMM = (128 * AS_STRIDE + 2 * 32 * WS_STRIDE) * 4;  // 102400 B
    cudaFuncSetAttribute(gemm_kernel,
                         cudaFuncAttributeMaxDynamicSharedMemorySize, SMEM_GEMM);

    // 1) prep: W split + binned fill (g_cnt zero on entry)
    int prep_threads = N_EDGES / 4;
    prep_kernel<<<(prep_threads + 255) / 256, 256>>>(Wm, src_idx, dst_idx);

    // 2) gather: one warp per node, no smem, no barriers
    int gather_blocks = (N_NODES * 32 + 255) / 256;   // 6250
    gather_kernel<<<gather_blocks, 256>>>(feature);

    // 3) GEMM + bias + relu
    int gemm_blocks = (N_NODES + 127) / 128;          // 391
    gemm_kernel<<<gemm_blocks, 256, SMEM_GEMM>>>(bias, out);
}